// round 7
// baseline (speedup 1.0000x reference)
#include <cuda_runtime.h>
#include <cstdint>

#define N_PRE    50000
#define VEC_DIM  300
#define HIDDEN   128
#define IN_SIZE  50000
#define N_TOKENS (64 * 200)          // 12800
#define VEC_BYTES    1200            // 300 f32
#define ROW_BYTES    1712            // 428 f32
#define TOK_PER_WARP 2
#define WARPS        4
#define TOK_PER_BLK  (TOK_PER_WARP * WARPS)   // 8
#define NBLK         (N_TOKENS / TOK_PER_BLK) // 1600

static __device__ __forceinline__ uint32_t smem_u32(const void* p) {
    uint32_t a;
    asm("{ .reg .u64 t; cvta.to.shared.u64 t, %1; cvt.u32.u64 %0, t; }"
        : "=r"(a) : "l"(p));
    return a;
}

// Streaming via bulk-async path (mbarrier-tracked, bypasses per-SM LDG MSHR cap):
//   pre token : cp.async.bulk G->S of its 1200B vector row; STS bias tail;
//   oov token : STS zeros + (b + W-column LDG gather) into smem;
//   all rows  : one cp.async.bulk S->G of the 1712B output row.
__global__ __launch_bounds__(128) void encoder_kernel(
    const int*    __restrict__ tokens,
    const float*  __restrict__ vectors,   // [N_PRE * 300]
    const float*  __restrict__ W,         // [HIDDEN, IN_SIZE]
    const float4* __restrict__ b4,        // [32]
    float*        __restrict__ out)       // [N_TOKENS * 428]
{
    __shared__ __align__(8)  unsigned long long mbar[WARPS];
    __shared__ __align__(16) unsigned char buf[TOK_PER_BLK * ROW_BYTES];

    const int lane = threadIdx.x & 31;
    const int warp = threadIdx.x >> 5;

    if (threadIdx.x < WARPS) {
        asm volatile("mbarrier.init.shared.b64 [%0], %1;"
                     :: "r"(smem_u32(&mbar[threadIdx.x])), "r"(1) : "memory");
    }
    __syncthreads();

    const int tbase = (blockIdx.x * WARPS + warp) * TOK_PER_WARP;
    const int tok0 = __ldg(&tokens[tbase]);
    const int tok1 = __ldg(&tokens[tbase + 1]);
    const bool pre0 = tok0 < N_PRE;
    const bool pre1 = tok1 < N_PRE;

    unsigned char* slot0p = buf + (size_t)(warp * TOK_PER_WARP) * ROW_BYTES;
    unsigned char* slot1p = slot0p + ROW_BYTES;
    const uint32_t slot0 = smem_u32(slot0p);
    const uint32_t slot1 = slot0 + ROW_BYTES;
    const uint32_t mb    = smem_u32(&mbar[warp]);

    // ---- issue bulk loads for pre tokens (lane 0) ----
    if (lane == 0) {
        const unsigned tx = (pre0 ? VEC_BYTES : 0) + (pre1 ? VEC_BYTES : 0);
        asm volatile("mbarrier.arrive.expect_tx.shared.b64 _, [%0], %1;"
                     :: "r"(mb), "r"(tx) : "memory");
        if (pre0) {
            const float* src = vectors + (size_t)tok0 * VEC_DIM;
            asm volatile(
                "cp.async.bulk.shared::cta.global.mbarrier::complete_tx::bytes "
                "[%0], [%1], %2, [%3];"
                :: "r"(slot0), "l"(src), "r"(VEC_BYTES), "r"(mb) : "memory");
        }
        if (pre1) {
            const float* src = vectors + (size_t)tok1 * VEC_DIM;
            asm volatile(
                "cp.async.bulk.shared::cta.global.mbarrier::complete_tx::bytes "
                "[%0], [%1], %2, [%3];"
                :: "r"(slot1), "l"(src), "r"(VEC_BYTES), "r"(mb) : "memory");
        }
    }

    // ---- build hidden part (+ zeros for oov vector part) in smem ----
    const float4 bb = __ldg(&b4[lane]);     // b[4*lane .. 4*lane+3]
    const float4 z  = make_float4(0.f, 0.f, 0.f, 0.f);

    {   // token 0
        float4 h = bb;
        if (!pre0) {
            const int c = tok0 - N_PRE;
            const float* Wc = W + c + (size_t)(4 * lane) * IN_SIZE;
            h.x += __ldg(Wc);
            h.y += __ldg(Wc + (size_t)IN_SIZE);
            h.z += __ldg(Wc + (size_t)2 * IN_SIZE);
            h.w += __ldg(Wc + (size_t)3 * IN_SIZE);
            float4* v4 = reinterpret_cast<float4*>(slot0p);
            v4[lane] = z; v4[lane + 32] = z;
            if (lane < 11) v4[lane + 64] = z;   // 75 float4 total
        }
        reinterpret_cast<float4*>(slot0p + VEC_BYTES)[lane] = h;
    }
    {   // token 1
        float4 h = bb;
        if (!pre1) {
            const int c = tok1 - N_PRE;
            const float* Wc = W + c + (size_t)(4 * lane) * IN_SIZE;
            h.x += __ldg(Wc);
            h.y += __ldg(Wc + (size_t)IN_SIZE);
            h.z += __ldg(Wc + (size_t)2 * IN_SIZE);
            h.w += __ldg(Wc + (size_t)3 * IN_SIZE);
            float4* v4 = reinterpret_cast<float4*>(slot1p);
            v4[lane] = z; v4[lane + 32] = z;
            if (lane < 11) v4[lane + 64] = z;
        }
        reinterpret_cast<float4*>(slot1p + VEC_BYTES)[lane] = h;
    }

    // ---- wait for bulk loads (parity 0, first & only phase this launch) ----
    {
        uint32_t done;
        asm volatile(
            "{ .reg .pred p;\n"
            "  mbarrier.try_wait.parity.shared.b64 p, [%1], %2;\n"
            "  selp.b32 %0, 1, 0, p; }"
            : "=r"(done) : "r"(mb), "r"(0u) : "memory");
        if (!done) {
            asm volatile(
                "{ .reg .pred P1;\n"
                "WL_%=:\n"
                "  mbarrier.try_wait.parity.shared.b64 P1, [%0], %1;\n"
                "  @P1 bra.uni WD_%=;\n"
                "  bra.uni WL_%=;\n"
                "WD_%=: }"
                :: "r"(mb), "r"(0u) : "memory");
        }
    }
    __syncwarp();

    // ---- bulk store both 1712B output rows (lane 0) ----
    if (lane == 0) {
        asm volatile("fence.proxy.async.shared::cta;" ::: "memory");
        float* dst0 = out + (size_t)tbase * 428;
        float* dst1 = dst0 + 428;
        asm volatile("cp.async.bulk.global.shared::cta.bulk_group [%0], [%1], %2;"
                     :: "l"(dst0), "r"(slot0), "r"(ROW_BYTES) : "memory");
        asm volatile("cp.async.bulk.global.shared::cta.bulk_group [%0], [%1], %2;"
                     :: "l"(dst1), "r"(slot1), "r"(ROW_BYTES) : "memory");
        asm volatile("cp.async.bulk.commit_group;" ::: "memory");
        asm volatile("cp.async.bulk.wait_group 0;" ::: "memory");
    }
}

extern "C" void kernel_launch(void* const* d_in, const int* in_sizes, int n_in,
                              void* d_out, int out_size)
{
    const int*    tokens  = (const int*)   d_in[0];
    const float*  vectors = (const float*) d_in[1];
    const float*  W       = (const float*) d_in[2];
    const float4* b       = (const float4*)d_in[3];
    float*        out     = (float*)       d_out;

    encoder_kernel<<<NBLK, 128>>>(tokens, vectors, W, b, out);
}